// round 1
// baseline (speedup 1.0000x reference)
#include <cuda_runtime.h>
#include <cuda_bf16.h>
#include <math.h>

#define N_NODES  100000
#define N_EDGES  1600000
#define N_GRAPHS 2000
#define IN_FEATS 128
#define HID      256
#define CLS_HID  128

// ---------------- scratch (static device memory; no allocations) ----------------
__device__ float g_hn[(size_t)N_NODES * HID];   // (h @ W) * norm_src_node[row]
__device__ float g_agg[(size_t)N_NODES * HID];  // scatter target; becomes h after finalize
__device__ float g_nsrc[N_NODES];               // out-degree -> rsqrt norm
__device__ float g_ndst[N_NODES];               // in-degree  -> rsqrt norm
__device__ float g_max[N_GRAPHS * HID];
__device__ float g_sum[N_GRAPHS * HID];
__device__ float g_cnt[N_GRAPHS];

// ---------------- zeroing ----------------
__global__ void zero_deg_kernel() {
    int i = blockIdx.x * blockDim.x + threadIdx.x;
    if (i < N_NODES) { g_nsrc[i] = 0.f; g_ndst[i] = 0.f; }
}

__global__ void zero_agg_kernel() {
    int i = blockIdx.x * blockDim.x + threadIdx.x;   // over N_NODES*HID/4 float4
    if (i < N_NODES * (HID / 4)) {
        ((float4*)g_agg)[i] = make_float4(0.f, 0.f, 0.f, 0.f);
    }
}

// ---------------- degrees / norms ----------------
__global__ void degree_kernel(const int* __restrict__ src, const int* __restrict__ dst) {
    int e = blockIdx.x * blockDim.x + threadIdx.x;
    if (e < N_EDGES) {
        atomicAdd(&g_nsrc[src[e]], 1.f);
        atomicAdd(&g_ndst[dst[e]], 1.f);
    }
}

__global__ void norm_kernel() {
    int i = blockIdx.x * blockDim.x + threadIdx.x;
    if (i < N_NODES) {
        g_nsrc[i] = rsqrtf(fmaxf(g_nsrc[i], 1.f));
        g_ndst[i] = rsqrtf(fmaxf(g_ndst[i], 1.f));
    }
}

// ---------------- GEMM + src-norm scale: g_hn[m][n] = nsrc[m] * sum_k A[m][k] W[k][n] ----------------
// BM=128, BN=64, BK=16, 256 threads, thread tile 8x4
template<int K>
__global__ void gemm_scale_kernel(const float* __restrict__ A,
                                  const float* __restrict__ W) {
    __shared__ float As[16][128];
    __shared__ float Bs[16][64];

    const int tid = threadIdx.x;
    const int block_m = blockIdx.x * 128;
    const int block_n = blockIdx.y * 64;

    const int tx = tid & 15;   // n-tile: cols tx*4 .. tx*4+3
    const int ty = tid >> 4;   // m-tile: rows ty*8 .. ty*8+7

    float acc[8][4];
    #pragma unroll
    for (int i = 0; i < 8; i++)
        #pragma unroll
        for (int j = 0; j < 4; j++) acc[i][j] = 0.f;

    for (int k0 = 0; k0 < K; k0 += 16) {
        // load A tile: 128x16 = 512 float4, 2 per thread
        #pragma unroll
        for (int i = 0; i < 2; i++) {
            int idx = tid + i * 256;
            int r   = idx >> 2;          // 0..127
            int c4  = (idx & 3) * 4;     // 0,4,8,12
            int gm  = block_m + r;
            float4 v = make_float4(0.f, 0.f, 0.f, 0.f);
            if (gm < N_NODES) v = *(const float4*)(A + (size_t)gm * K + k0 + c4);
            As[c4 + 0][r] = v.x; As[c4 + 1][r] = v.y;
            As[c4 + 2][r] = v.z; As[c4 + 3][r] = v.w;
        }
        // load W tile: 16x64 = 256 float4, 1 per thread
        {
            int r  = tid >> 4;           // 0..15
            int c4 = (tid & 15) * 4;     // 0..60
            float4 v = *(const float4*)(W + (size_t)(k0 + r) * HID + block_n + c4);
            *(float4*)&Bs[r][c4] = v;
        }
        __syncthreads();

        #pragma unroll
        for (int k = 0; k < 16; k++) {
            float a[8], b[4];
            #pragma unroll
            for (int i = 0; i < 8; i++) a[i] = As[k][ty * 8 + i];
            #pragma unroll
            for (int j = 0; j < 4; j++) b[j] = Bs[k][tx * 4 + j];
            #pragma unroll
            for (int i = 0; i < 8; i++)
                #pragma unroll
                for (int j = 0; j < 4; j++)
                    acc[i][j] += a[i] * b[j];
        }
        __syncthreads();
    }

    #pragma unroll
    for (int i = 0; i < 8; i++) {
        int gm = block_m + ty * 8 + i;
        if (gm < N_NODES) {
            float s = g_nsrc[gm];
            float4 v = make_float4(acc[i][0] * s, acc[i][1] * s,
                                   acc[i][2] * s, acc[i][3] * s);
            *(float4*)(g_hn + (size_t)gm * HID + block_n + tx * 4) = v;
        }
    }
}

// ---------------- edge scatter-add: agg[dst] += hn[src]  (warp per edge, RED.128) ----------------
__global__ void scatter_kernel(const int* __restrict__ src, const int* __restrict__ dst) {
    int gtid = blockIdx.x * blockDim.x + threadIdx.x;
    int e    = gtid >> 5;
    if (e >= N_EDGES) return;
    int lane = gtid & 31;
    int s = src[e];
    int d = dst[e];
    const float4* p = (const float4*)(g_hn + (size_t)s * HID);
    float4*       q = (float4*)(g_agg + (size_t)d * HID);
    float4 v0 = p[lane];
    float4 v1 = p[lane + 32];
    atomicAdd(q + lane,      v0);   // sm_90+ vector red.add.v4.f32 (no return use)
    atomicAdd(q + lane + 32, v1);
}

// ---------------- finalize: h = relu(agg * norm_dst + b), in place in g_agg ----------------
__global__ void finalize_kernel(const float* __restrict__ b) {
    int i = blockIdx.x * blockDim.x + threadIdx.x;  // over N_NODES*64 float4
    if (i >= N_NODES * (HID / 4)) return;
    int node = i >> 6;
    int c4   = (i & 63) * 4;
    float nd = g_ndst[node];
    float4 v = ((float4*)g_agg)[i];
    v.x = fmaxf(v.x * nd + b[c4 + 0], 0.f);
    v.y = fmaxf(v.y * nd + b[c4 + 1], 0.f);
    v.z = fmaxf(v.z * nd + b[c4 + 2], 0.f);
    v.w = fmaxf(v.w * nd + b[c4 + 3], 0.f);
    ((float4*)g_agg)[i] = v;
}

// ---------------- readout: graph_id is SORTED -> per-graph contiguous ranges ----------------
__device__ __forceinline__ int lower_bound_dev(const int* a, int n, int key) {
    int lo = 0, hi = n;
    while (lo < hi) {
        int mid = (lo + hi) >> 1;
        if (a[mid] < key) lo = mid + 1; else hi = mid;
    }
    return lo;
}

__global__ void pool_kernel(const int* __restrict__ gid) {
    int g = blockIdx.x;                 // 0..N_GRAPHS-1
    int f = threadIdx.x;                // 0..255 feature
    int start = lower_bound_dev(gid, N_NODES, g);
    int end   = lower_bound_dev(gid, N_NODES, g + 1);
    float mx = 0.f, sm = 0.f;           // relu output >= 0, so 0-init max matches
    for (int n = start; n < end; n++) { //   jnp.where(isfinite, max, 0) semantics
        float v = g_agg[(size_t)n * HID + f];
        mx = fmaxf(mx, v);
        sm += v;
    }
    g_max[g * HID + f] = mx;
    g_sum[g * HID + f] = sm;
    if (f == 0) g_cnt[g] = (float)(end - start);
}

// ---------------- classifier: g_rep = softmax(pool_w) . (max, avg); MLP 256->128->2 ----------------
__global__ void classifier_kernel(const float* __restrict__ pool_w,
                                  const float* __restrict__ fc1_w,
                                  const float* __restrict__ fc1_b,
                                  const float* __restrict__ fc2_w,
                                  const float* __restrict__ fc2_b,
                                  float* __restrict__ out) {
    int g = blockIdx.x;
    int t = threadIdx.x;  // 0..127
    __shared__ float rep[HID];
    __shared__ float red0[CLS_HID], red1[CLS_HID];

    float p0 = pool_w[0], p1 = pool_w[1];
    float mp = fmaxf(p0, p1);
    float e0 = expf(p0 - mp), e1 = expf(p1 - mp);
    float w0 = e0 / (e0 + e1), w1 = e1 / (e0 + e1);
    float inv = 1.f / fmaxf(g_cnt[g], 1.f);

    for (int i = t; i < HID; i += CLS_HID)
        rep[i] = w0 * g_max[g * HID + i] + w1 * g_sum[g * HID + i] * inv;
    __syncthreads();

    float acc = fc1_b[t];
    #pragma unroll 8
    for (int k = 0; k < HID; k++)
        acc += rep[k] * fc1_w[k * CLS_HID + t];
    float x = fmaxf(acc, 0.f);

    red0[t] = x * fc2_w[t * 2 + 0];
    red1[t] = x * fc2_w[t * 2 + 1];
    __syncthreads();
    for (int s = CLS_HID / 2; s > 0; s >>= 1) {
        if (t < s) { red0[t] += red0[t + s]; red1[t] += red1[t + s]; }
        __syncthreads();
    }
    if (t == 0) {
        out[g * 2 + 0] = red0[0] + fc2_b[0];
        out[g * 2 + 1] = red1[0] + fc2_b[1];
    }
}

// ---------------- launch ----------------
extern "C" void kernel_launch(void* const* d_in, const int* in_sizes, int n_in,
                              void* d_out, int out_size) {
    const float *features, *W1, *b1, *W2, *b2, *W3, *b3, *pool_w;
    const float *fc1_w, *fc1_b, *fc2_w, *fc2_b;
    const int *src, *dst, *gid;

    if (in_sizes[1] == N_EDGES) {
        // setup_inputs dict order:
        // features, src, dst, graph_id, W1, b1, W2, b2, W3, b3, pool_w, fc1_w, fc1_b, fc2_w, fc2_b
        features = (const float*)d_in[0];
        src      = (const int*)d_in[1];
        dst      = (const int*)d_in[2];
        gid      = (const int*)d_in[3];
        W1 = (const float*)d_in[4];  b1 = (const float*)d_in[5];
        W2 = (const float*)d_in[6];  b2 = (const float*)d_in[7];
        W3 = (const float*)d_in[8];  b3 = (const float*)d_in[9];
        pool_w = (const float*)d_in[10];
        fc1_w = (const float*)d_in[11]; fc1_b = (const float*)d_in[12];
        fc2_w = (const float*)d_in[13]; fc2_b = (const float*)d_in[14];
    } else {
        // reference() signature order:
        // features, W1, b1, W2, b2, W3, b3, pool_w, fc1_w, fc1_b, fc2_w, fc2_b, src, dst, graph_id
        features = (const float*)d_in[0];
        W1 = (const float*)d_in[1];  b1 = (const float*)d_in[2];
        W2 = (const float*)d_in[3];  b2 = (const float*)d_in[4];
        W3 = (const float*)d_in[5];  b3 = (const float*)d_in[6];
        pool_w = (const float*)d_in[7];
        fc1_w = (const float*)d_in[8];  fc1_b = (const float*)d_in[9];
        fc2_w = (const float*)d_in[10]; fc2_b = (const float*)d_in[11];
        src = (const int*)d_in[12];
        dst = (const int*)d_in[13];
        gid = (const int*)d_in[14];
    }

    const int NTHD = 256;
    const int node_blocks = (N_NODES + NTHD - 1) / NTHD;               // 391
    const int edge_blocks = (N_EDGES + NTHD - 1) / NTHD;               // 6250
    const int vec_blocks  = (N_NODES * (HID / 4) + NTHD - 1) / NTHD;   // 25000
    const int warp_blocks = (N_EDGES * 32 + NTHD - 1) / NTHD;          // 200000

    // degrees -> norms
    zero_deg_kernel<<<node_blocks, NTHD>>>();
    degree_kernel<<<edge_blocks, NTHD>>>(src, dst);
    norm_kernel<<<node_blocks, NTHD>>>();

    dim3 gemm_grid((N_NODES + 127) / 128, HID / 64);  // (782, 4)

    // layer 1 (K = IN_FEATS)
    gemm_scale_kernel<IN_FEATS><<<gemm_grid, 256>>>(features, W1);
    zero_agg_kernel<<<vec_blocks, NTHD>>>();
    scatter_kernel<<<warp_blocks, NTHD>>>(src, dst);
    finalize_kernel<<<vec_blocks, NTHD>>>(b1);

    // layer 2 (K = HID), A = g_agg (device symbol address)
    float* agg_ptr = nullptr;
    cudaGetSymbolAddress((void**)&agg_ptr, g_agg);

    gemm_scale_kernel<HID><<<gemm_grid, 256>>>(agg_ptr, W2);
    zero_agg_kernel<<<vec_blocks, NTHD>>>();
    scatter_kernel<<<warp_blocks, NTHD>>>(src, dst);
    finalize_kernel<<<vec_blocks, NTHD>>>(b2);

    // layer 3
    gemm_scale_kernel<HID><<<gemm_grid, 256>>>(agg_ptr, W3);
    zero_agg_kernel<<<vec_blocks, NTHD>>>();
    scatter_kernel<<<warp_blocks, NTHD>>>(src, dst);
    finalize_kernel<<<vec_blocks, NTHD>>>(b3);

    // readout + classifier
    pool_kernel<<<N_GRAPHS, HID>>>(gid);
    classifier_kernel<<<N_GRAPHS, CLS_HID>>>(pool_w, fc1_w, fc1_b, fc2_w, fc2_b,
                                             (float*)d_out);
}

// round 2
// speedup vs baseline: 1.7979x; 1.7979x over previous
#include <cuda_runtime.h>
#include <cuda_bf16.h>
#include <math.h>

#define N_NODES  100000
#define N_EDGES  1600000
#define N_GRAPHS 2000
#define IN_FEATS 128
#define HID      256
#define CLS_HID  128

#define SCAN_BLK 1024
#define N_SCAN_BLOCKS ((N_NODES + SCAN_BLK - 1) / SCAN_BLK)   // 98

// ---------------- scratch (static device memory; no allocations) ----------------
__device__ float g_hn[(size_t)N_NODES * HID];   // (h @ W) * norm_src_node[row]
__device__ float g_h [(size_t)N_NODES * HID];   // layer output (post agg+bias+relu)
__device__ float g_nsrc[N_NODES];
__device__ float g_ndst[N_NODES];
__device__ int   g_outdeg[N_NODES];
__device__ int   g_indeg [N_NODES];
__device__ int   g_row_off[N_NODES + 1];
__device__ int   g_cursor [N_NODES];
__device__ int   g_esrc   [N_EDGES];
__device__ int   g_bsum   [N_SCAN_BLOCKS];
__device__ float g_max[N_GRAPHS * HID];
__device__ float g_sum[N_GRAPHS * HID];
__device__ float g_cnt[N_GRAPHS];

// ---------------- f32x2 packed-FMA helpers (Blackwell) ----------------
__device__ __forceinline__ void fma2(unsigned long long& d,
                                     unsigned long long a,
                                     unsigned long long b) {
    asm("fma.rn.f32x2 %0, %1, %2, %0;" : "+l"(d) : "l"(a), "l"(b));
}
__device__ __forceinline__ unsigned long long bcast2(float x) {
    unsigned long long r;
    asm("mov.b64 %0, {%1, %1};" : "=l"(r) : "r"(__float_as_uint(x)));
    return r;
}
__device__ __forceinline__ float f2_lo(unsigned long long v) {
    return __uint_as_float((unsigned)v);
}
__device__ __forceinline__ float f2_hi(unsigned long long v) {
    return __uint_as_float((unsigned)(v >> 32));
}

// ---------------- degrees / norms / CSR build ----------------
__global__ void zero_counts_kernel() {
    int i = blockIdx.x * blockDim.x + threadIdx.x;
    if (i < N_NODES) { g_outdeg[i] = 0; g_indeg[i] = 0; }
}

__global__ void degree_kernel(const int* __restrict__ src, const int* __restrict__ dst) {
    int e = blockIdx.x * blockDim.x + threadIdx.x;
    if (e < N_EDGES) {
        atomicAdd(&g_outdeg[src[e]], 1);
        atomicAdd(&g_indeg[dst[e]], 1);
    }
}

__global__ void norm_kernel() {
    int i = blockIdx.x * blockDim.x + threadIdx.x;
    if (i < N_NODES) {
        g_nsrc[i] = rsqrtf(fmaxf((float)g_outdeg[i], 1.f));
        g_ndst[i] = rsqrtf(fmaxf((float)g_indeg[i], 1.f));
    }
}

// per-block exclusive scan of indeg -> row_off (partial), block totals -> g_bsum
__global__ void scan1_kernel() {
    __shared__ int sh[SCAN_BLK];
    int tid = threadIdx.x;
    int i = blockIdx.x * SCAN_BLK + tid;
    int v = (i < N_NODES) ? g_indeg[i] : 0;
    sh[tid] = v;
    __syncthreads();
    #pragma unroll
    for (int d = 1; d < SCAN_BLK; d <<= 1) {
        int t = (tid >= d) ? sh[tid - d] : 0;
        __syncthreads();
        sh[tid] += t;
        __syncthreads();
    }
    if (i < N_NODES) g_row_off[i] = sh[tid] - v;     // exclusive
    if (tid == SCAN_BLK - 1) g_bsum[blockIdx.x] = sh[tid];
}

// serial scan of block sums (98 values; trivial)
__global__ void scan2_kernel() {
    if (threadIdx.x == 0) {
        int acc = 0;
        for (int b = 0; b < N_SCAN_BLOCKS; b++) {
            int t = g_bsum[b];
            g_bsum[b] = acc;
            acc += t;
        }
    }
}

__global__ void scan3_kernel() {
    int i = blockIdx.x * blockDim.x + threadIdx.x;
    if (i < N_NODES) {
        int off = g_row_off[i] + g_bsum[i / SCAN_BLK];
        g_row_off[i] = off;
        g_cursor[i]  = off;
    }
    if (i == 0) g_row_off[N_NODES] = N_EDGES;
}

__global__ void place_kernel(const int* __restrict__ src, const int* __restrict__ dst) {
    int e = blockIdx.x * blockDim.x + threadIdx.x;
    if (e < N_EDGES) {
        int d = dst[e];
        int idx = atomicAdd(&g_cursor[d], 1);
        g_esrc[idx] = src[e];
    }
}

// ---------------- GEMM + src-norm scale (f32x2 packed FMA) ----------------
// BM=128, BN=64, BK=16, 256 threads, thread tile 8 rows (4 pairs) x 4 cols
template<int K>
__global__ void gemm_scale_kernel(const float* __restrict__ A,
                                  const float* __restrict__ W) {
    __shared__ float As[16][128];
    __shared__ float Bs[16][64];

    const int tid = threadIdx.x;
    const int block_m = blockIdx.x * 128;
    const int block_n = blockIdx.y * 64;

    const int tx = tid & 15;   // cols tx*4 .. +3
    const int ty = tid >> 4;   // rows ty*8 .. +7  (4 packed pairs)

    unsigned long long acc[4][4];
    #pragma unroll
    for (int i = 0; i < 4; i++)
        #pragma unroll
        for (int j = 0; j < 4; j++) acc[i][j] = 0ull;

    for (int k0 = 0; k0 < K; k0 += 16) {
        // A tile: 128x16 = 512 float4, 2 per thread
        #pragma unroll
        for (int i = 0; i < 2; i++) {
            int idx = tid + i * 256;
            int r   = idx >> 2;
            int c4  = (idx & 3) * 4;
            int gm  = block_m + r;
            float4 v = make_float4(0.f, 0.f, 0.f, 0.f);
            if (gm < N_NODES) v = *(const float4*)(A + (size_t)gm * K + k0 + c4);
            As[c4 + 0][r] = v.x; As[c4 + 1][r] = v.y;
            As[c4 + 2][r] = v.z; As[c4 + 3][r] = v.w;
        }
        // W tile: 16x64 = 256 float4, 1 per thread
        {
            int r  = tid >> 4;
            int c4 = (tid & 15) * 4;
            float4 v = *(const float4*)(W + (size_t)(k0 + r) * HID + block_n + c4);
            *(float4*)&Bs[r][c4] = v;
        }
        __syncthreads();

        #pragma unroll
        for (int k = 0; k < 16; k++) {
            unsigned long long ap[4];   // row pairs via LDS.64
            #pragma unroll
            for (int i = 0; i < 4; i++)
                ap[i] = *(const unsigned long long*)&As[k][ty * 8 + 2 * i];
            unsigned long long bb[4];   // col broadcast pairs
            #pragma unroll
            for (int j = 0; j < 4; j++)
                bb[j] = bcast2(Bs[k][tx * 4 + j]);
            #pragma unroll
            for (int i = 0; i < 4; i++)
                #pragma unroll
                for (int j = 0; j < 4; j++)
                    fma2(acc[i][j], ap[i], bb[j]);
        }
        __syncthreads();
    }

    #pragma unroll
    for (int i = 0; i < 4; i++) {
        int gm0 = block_m + ty * 8 + 2 * i;
        if (gm0 < N_NODES) {
            float s0 = g_nsrc[gm0];
            float4 v0 = make_float4(f2_lo(acc[i][0]) * s0, f2_lo(acc[i][1]) * s0,
                                    f2_lo(acc[i][2]) * s0, f2_lo(acc[i][3]) * s0);
            *(float4*)(g_hn + (size_t)gm0 * HID + block_n + tx * 4) = v0;
        }
        int gm1 = gm0 + 1;
        if (gm1 < N_NODES) {
            float s1 = g_nsrc[gm1];
            float4 v1 = make_float4(f2_hi(acc[i][0]) * s1, f2_hi(acc[i][1]) * s1,
                                    f2_hi(acc[i][2]) * s1, f2_hi(acc[i][3]) * s1);
            *(float4*)(g_hn + (size_t)gm1 * HID + block_n + tx * 4) = v1;
        }
    }
}

// ---------------- CSR aggregation + norm_dst + bias + relu (fused) ----------------
// warp per dst node; lane covers float4 slots [lane] and [lane+32] of the 256-wide row
__global__ void agg_kernel(const float* __restrict__ b) {
    int warp = (blockIdx.x * blockDim.x + threadIdx.x) >> 5;
    if (warp >= N_NODES) return;
    int lane = threadIdx.x & 31;
    int beg = g_row_off[warp];
    int end = g_row_off[warp + 1];

    float4 a0 = make_float4(0.f, 0.f, 0.f, 0.f);
    float4 a1 = make_float4(0.f, 0.f, 0.f, 0.f);
    for (int i = beg; i < end; i++) {
        int s = g_esrc[i];
        const float4* p = (const float4*)(g_hn + (size_t)s * HID);
        float4 v0 = p[lane];
        float4 v1 = p[lane + 32];
        a0.x += v0.x; a0.y += v0.y; a0.z += v0.z; a0.w += v0.w;
        a1.x += v1.x; a1.y += v1.y; a1.z += v1.z; a1.w += v1.w;
    }
    float nd = g_ndst[warp];
    float4 b0 = *(const float4*)(b + lane * 4);
    float4 b1 = *(const float4*)(b + (lane + 32) * 4);
    a0.x = fmaxf(a0.x * nd + b0.x, 0.f); a0.y = fmaxf(a0.y * nd + b0.y, 0.f);
    a0.z = fmaxf(a0.z * nd + b0.z, 0.f); a0.w = fmaxf(a0.w * nd + b0.w, 0.f);
    a1.x = fmaxf(a1.x * nd + b1.x, 0.f); a1.y = fmaxf(a1.y * nd + b1.y, 0.f);
    a1.z = fmaxf(a1.z * nd + b1.z, 0.f); a1.w = fmaxf(a1.w * nd + b1.w, 0.f);
    float4* q = (float4*)(g_h + (size_t)warp * HID);
    q[lane]      = a0;
    q[lane + 32] = a1;
}

// ---------------- readout ----------------
__device__ __forceinline__ int lower_bound_dev(const int* a, int n, int key) {
    int lo = 0, hi = n;
    while (lo < hi) {
        int mid = (lo + hi) >> 1;
        if (a[mid] < key) lo = mid + 1; else hi = mid;
    }
    return lo;
}

__global__ void pool_kernel(const int* __restrict__ gid) {
    int g = blockIdx.x;
    int f = threadIdx.x;
    int start = lower_bound_dev(gid, N_NODES, g);
    int end   = lower_bound_dev(gid, N_NODES, g + 1);
    float mx = 0.f, sm = 0.f;   // relu output >= 0; empty-graph isfinite->0 matches
    for (int n = start; n < end; n++) {
        float v = g_h[(size_t)n * HID + f];
        mx = fmaxf(mx, v);
        sm += v;
    }
    g_max[g * HID + f] = mx;
    g_sum[g * HID + f] = sm;
    if (f == 0) g_cnt[g] = (float)(end - start);
}

// ---------------- classifier ----------------
__global__ void classifier_kernel(const float* __restrict__ pool_w,
                                  const float* __restrict__ fc1_w,
                                  const float* __restrict__ fc1_b,
                                  const float* __restrict__ fc2_w,
                                  const float* __restrict__ fc2_b,
                                  float* __restrict__ out) {
    int g = blockIdx.x;
    int t = threadIdx.x;  // 0..127
    __shared__ float rep[HID];
    __shared__ float red0[CLS_HID], red1[CLS_HID];

    float p0 = pool_w[0], p1 = pool_w[1];
    float mp = fmaxf(p0, p1);
    float e0 = expf(p0 - mp), e1 = expf(p1 - mp);
    float w0 = e0 / (e0 + e1), w1 = e1 / (e0 + e1);
    float inv = 1.f / fmaxf(g_cnt[g], 1.f);

    for (int i = t; i < HID; i += CLS_HID)
        rep[i] = w0 * g_max[g * HID + i] + w1 * g_sum[g * HID + i] * inv;
    __syncthreads();

    float acc = fc1_b[t];
    #pragma unroll 8
    for (int k = 0; k < HID; k++)
        acc += rep[k] * fc1_w[k * CLS_HID + t];
    float x = fmaxf(acc, 0.f);

    red0[t] = x * fc2_w[t * 2 + 0];
    red1[t] = x * fc2_w[t * 2 + 1];
    __syncthreads();
    for (int s = CLS_HID / 2; s > 0; s >>= 1) {
        if (t < s) { red0[t] += red0[t + s]; red1[t] += red1[t + s]; }
        __syncthreads();
    }
    if (t == 0) {
        out[g * 2 + 0] = red0[0] + fc2_b[0];
        out[g * 2 + 1] = red1[0] + fc2_b[1];
    }
}

// ---------------- launch ----------------
extern "C" void kernel_launch(void* const* d_in, const int* in_sizes, int n_in,
                              void* d_out, int out_size) {
    const float *features, *W1, *b1, *W2, *b2, *W3, *b3, *pool_w;
    const float *fc1_w, *fc1_b, *fc2_w, *fc2_b;
    const int *src, *dst, *gid;

    if (in_sizes[1] == N_EDGES) {
        features = (const float*)d_in[0];
        src      = (const int*)d_in[1];
        dst      = (const int*)d_in[2];
        gid      = (const int*)d_in[3];
        W1 = (const float*)d_in[4];  b1 = (const float*)d_in[5];
        W2 = (const float*)d_in[6];  b2 = (const float*)d_in[7];
        W3 = (const float*)d_in[8];  b3 = (const float*)d_in[9];
        pool_w = (const float*)d_in[10];
        fc1_w = (const float*)d_in[11]; fc1_b = (const float*)d_in[12];
        fc2_w = (const float*)d_in[13]; fc2_b = (const float*)d_in[14];
    } else {
        features = (const float*)d_in[0];
        W1 = (const float*)d_in[1];  b1 = (const float*)d_in[2];
        W2 = (const float*)d_in[3];  b2 = (const float*)d_in[4];
        W3 = (const float*)d_in[5];  b3 = (const float*)d_in[6];
        pool_w = (const float*)d_in[7];
        fc1_w = (const float*)d_in[8];  fc1_b = (const float*)d_in[9];
        fc2_w = (const float*)d_in[10]; fc2_b = (const float*)d_in[11];
        src = (const int*)d_in[12];
        dst = (const int*)d_in[13];
        gid = (const int*)d_in[14];
    }

    const int NTHD = 256;
    const int node_blocks = (N_NODES + NTHD - 1) / NTHD;
    const int edge_blocks = (N_EDGES + NTHD - 1) / NTHD;
    const int agg_blocks  = (N_NODES * 32 + NTHD - 1) / NTHD;   // warp per node

    // degrees -> norms -> CSR
    zero_counts_kernel<<<node_blocks, NTHD>>>();
    degree_kernel<<<edge_blocks, NTHD>>>(src, dst);
    norm_kernel<<<node_blocks, NTHD>>>();
    scan1_kernel<<<N_SCAN_BLOCKS, SCAN_BLK>>>();
    scan2_kernel<<<1, 32>>>();
    scan3_kernel<<<node_blocks, NTHD>>>();
    place_kernel<<<edge_blocks, NTHD>>>(src, dst);

    dim3 gemm_grid((N_NODES + 127) / 128, HID / 64);

    float* h_ptr = nullptr;
    cudaGetSymbolAddress((void**)&h_ptr, g_h);

    // layer 1
    gemm_scale_kernel<IN_FEATS><<<gemm_grid, 256>>>(features, W1);
    agg_kernel<<<agg_blocks, NTHD>>>(b1);
    // layer 2
    gemm_scale_kernel<HID><<<gemm_grid, 256>>>(h_ptr, W2);
    agg_kernel<<<agg_blocks, NTHD>>>(b2);
    // layer 3
    gemm_scale_kernel<HID><<<gemm_grid, 256>>>(h_ptr, W3);
    agg_kernel<<<agg_blocks, NTHD>>>(b3);

    // readout + classifier
    pool_kernel<<<N_GRAPHS, HID>>>(gid);
    classifier_kernel<<<N_GRAPHS, CLS_HID>>>(pool_w, fc1_w, fc1_b, fc2_w, fc2_b,
                                             (float*)d_out);
}